// round 1
// baseline (speedup 1.0000x reference)
#include <cuda_runtime.h>
#include <float.h>
#include <math.h>

#define NNODES 2048
#define DIM    512
#define HIDD   256
#define NHEAD  4
#define TOPK   6
#define MAXD   256

// ---------------- scratch (device globals; no allocations allowed) ----------------
__device__ __align__(16) float g_Xn[NNODES * DIM];
__device__ __align__(16) float g_sq[NNODES];
__device__ __align__(16) float g_sim[NNODES * NNODES];
__device__ __align__(16) unsigned char g_adj[NNODES * NNODES];
__device__ int   g_nbr[NNODES * MAXD];
__device__ int   g_cnt[NNODES];
__device__ __align__(16) float g_Wpack[DIM * NHEAD * HIDD];
__device__ __align__(16) float g_Wh[NNODES * NHEAD * HIDD];
__device__ __align__(16) float g_s1[NHEAD * NNODES];
__device__ __align__(16) float g_s2[NHEAD * NNODES];
__device__ __align__(16) float g_hidden[NNODES * NHEAD * HIDD];
__device__ __align__(16) float g_WhO[NNODES * HIDD];
__device__ __align__(16) float g_sO1[NNODES];
__device__ __align__(16) float g_sO2[NNODES];
__device__ __align__(16) float g_pair[NNODES * 2 * HIDD];
__device__ __align__(16) float g_m1[NNODES * 512];
__device__ __align__(16) float g_m2[NNODES * 256];
__device__ __align__(16) float g_m3[NNODES * 128];

// ---------------- row norms ----------------
__global__ void rowstat_kernel(const float* __restrict__ X, float* __restrict__ Xn,
                               float* __restrict__ sq) {
    int i = blockIdx.x;
    int t = threadIdx.x;  // 256
    float s = 0.f;
    for (int d = t; d < DIM; d += 256) { float v = X[(size_t)i * DIM + d]; s += v * v; }
    __shared__ float sh[256];
    sh[t] = s; __syncthreads();
    for (int k = 128; k; k >>= 1) { if (t < k) sh[t] += sh[t + k]; __syncthreads(); }
    float tot = sh[0];
    if (t == 0) sq[i] = tot;
    if (Xn) {
        float inv = 1.0f / sqrtf(tot);
        for (int d = t; d < DIM; d += 256) Xn[(size_t)i * DIM + d] = X[(size_t)i * DIM + d] * inv;
    }
}

// ---------------- tiled SGEMM: C[M,Nc] = A[M,K] @ B (TB: B is [Nc,K] row-major) ----------------
template <int BM, int BN, int BK, int TM, int TN, bool TB>
__global__ void __launch_bounds__((BM / TM) * (BN / TN))
gemm_k(const float* __restrict__ A, const float* __restrict__ B, float* __restrict__ C,
       int M, int Nc, int K, const float* __restrict__ bias, int relu) {
    constexpr int NT = (BM / TM) * (BN / TN);
    constexpr int KV = BK / 4;
    __shared__ __align__(16) float As[BK][BM];
    __shared__ __align__(16) float Bs[BK][BN];
    const int tid = threadIdx.x;
    const int row0 = blockIdx.y * BM;
    const int col0 = blockIdx.x * BN;
    const int tx = tid % (BN / TN);
    const int ty = tid / (BN / TN);
    float acc[TM][TN];
#pragma unroll
    for (int m = 0; m < TM; m++)
#pragma unroll
        for (int n = 0; n < TN; n++) acc[m][n] = 0.f;

    for (int kk = 0; kk < K; kk += BK) {
        {
            constexpr int LA = (BM * KV) / NT;
#pragma unroll
            for (int l = 0; l < LA; l++) {
                int idx = tid + l * NT;
                int ar = idx / KV;
                int kc = (idx % KV) * 4;
                const float4 v = *(const float4*)(A + (size_t)(row0 + ar) * K + kk + kc);
                As[kc + 0][ar] = v.x; As[kc + 1][ar] = v.y;
                As[kc + 2][ar] = v.z; As[kc + 3][ar] = v.w;
            }
        }
        if (TB) {
            constexpr int LB = (BN * KV) / NT;
#pragma unroll
            for (int l = 0; l < LB; l++) {
                int idx = tid + l * NT;
                int bn = idx / KV;
                int kc = (idx % KV) * 4;
                const float4 v = *(const float4*)(B + (size_t)(col0 + bn) * K + kk + kc);
                Bs[kc + 0][bn] = v.x; Bs[kc + 1][bn] = v.y;
                Bs[kc + 2][bn] = v.z; Bs[kc + 3][bn] = v.w;
            }
        } else {
            constexpr int NV = BN / 4;
            constexpr int LB = (BK * NV) / NT;
#pragma unroll
            for (int l = 0; l < LB; l++) {
                int idx = tid + l * NT;
                int br = idx / NV;
                int nc = (idx % NV) * 4;
                *(float4*)&Bs[br][nc] = *(const float4*)(B + (size_t)(kk + br) * Nc + col0 + nc);
            }
        }
        __syncthreads();
#pragma unroll
        for (int k = 0; k < BK; k++) {
            float ar[TM], br[TN];
#pragma unroll
            for (int m = 0; m < TM; m++) ar[m] = As[k][ty * TM + m];
#pragma unroll
            for (int n = 0; n < TN; n++) br[n] = Bs[k][tx * TN + n];
#pragma unroll
            for (int m = 0; m < TM; m++)
#pragma unroll
                for (int n = 0; n < TN; n++) acc[m][n] += ar[m] * br[n];
        }
        __syncthreads();
    }
#pragma unroll
    for (int m = 0; m < TM; m++) {
        int r = row0 + ty * TM + m;
#pragma unroll
        for (int n = 0; n < TN; n++) {
            int c = col0 + tx * TN + n;
            float v = acc[m][n];
            if (bias) v += bias[c];
            if (relu) v = fmaxf(v, 0.f);
            C[(size_t)r * Nc + c] = v;
        }
    }
}

// ---------------- clear adjacency ----------------
__global__ void clear_adj(unsigned char* adj) {
    int idx = blockIdx.x * blockDim.x + threadIdx.x;  // 262144 threads for 4MB
    ((int4*)adj)[idx] = make_int4(0, 0, 0, 0);
}

// ---------------- per-row top-6 + edge writes ----------------
// mode 0: euclid — key = 2*dot - sq[j]; edge for any selected j != i
// mode 1: cosine — key = sim;           edge only if val > 0 and j != i
__device__ __forceinline__ bool tk_better(float v1, int i1, float v2, int i2) {
    return (v1 > v2) || (v1 == v2 && i1 < i2);
}
__global__ void topk_kernel(const float* __restrict__ sim, const float* __restrict__ sq,
                            unsigned char* __restrict__ adj, int mode) {
    int i = blockIdx.x;
    int t = threadIdx.x;  // 128
    float bv[TOPK]; int bi[TOPK];
#pragma unroll
    for (int k = 0; k < TOPK; k++) { bv[k] = -FLT_MAX; bi[k] = 0x7fffffff; }
    for (int c = t; c < NNODES; c += 128) {
        float d = sim[(size_t)i * NNODES + c];
        float key = (mode == 0) ? (2.f * d - sq[c]) : d;
        if (tk_better(key, c, bv[TOPK - 1], bi[TOPK - 1])) {
            bv[TOPK - 1] = key; bi[TOPK - 1] = c;
#pragma unroll
            for (int k = TOPK - 1; k > 0; k--) {
                if (tk_better(bv[k], bi[k], bv[k - 1], bi[k - 1])) {
                    float tv = bv[k]; bv[k] = bv[k - 1]; bv[k - 1] = tv;
                    int ti = bi[k]; bi[k] = bi[k - 1]; bi[k - 1] = ti;
                } else break;
            }
        }
    }
    __shared__ float rv[128]; __shared__ int ri[128]; __shared__ int rt[128];
    __shared__ float winv[TOPK]; __shared__ int wini[TOPK];
    int p = 0;
    for (int r = 0; r < TOPK; r++) {
        rv[t] = (p < TOPK) ? bv[p] : -FLT_MAX;
        ri[t] = (p < TOPK) ? bi[p] : 0x7fffffff;
        rt[t] = t;
        __syncthreads();
        for (int s = 64; s; s >>= 1) {
            if (t < s) {
                if (tk_better(rv[t + s], ri[t + s], rv[t], ri[t])) {
                    rv[t] = rv[t + s]; ri[t] = ri[t + s]; rt[t] = rt[t + s];
                }
            }
            __syncthreads();
        }
        if (t == 0) { winv[r] = rv[0]; wini[r] = ri[0]; }
        if (t == rt[0]) p++;
        __syncthreads();
    }
    if (t == 0) {
        for (int r = 0; r < TOPK; r++) {
            int j = wini[r];
            if (j == i) continue;
            if (mode == 1 && !(winv[r] > 0.f)) continue;
            adj[(size_t)i * NNODES + j] = 1;
            adj[(size_t)j * NNODES + i] = 1;
        }
    }
}

// ---------------- compact adjacency rows into neighbor lists ----------------
__global__ void build_nbr_kernel(const unsigned char* __restrict__ adj,
                                 int* __restrict__ nbr, int* __restrict__ cnt) {
    int i = blockIdx.x;
    int t = threadIdx.x;  // 256, each scans 8 contiguous columns
    int local[8]; int lc = 0;
    int base = t * 8;
#pragma unroll
    for (int k = 0; k < 8; k++) {
        int c = base + k;
        if (adj[(size_t)i * NNODES + c]) { local[lc++] = c; }
    }
    __shared__ int sh[256];
    __shared__ int off[256];
    sh[t] = lc; __syncthreads();
    if (t == 0) {
        int run = 0;
        for (int k = 0; k < 256; k++) { off[k] = run; run += sh[k]; }
        cnt[i] = run > MAXD ? MAXD : run;
    }
    __syncthreads();
    int o = off[t];
    for (int k = 0; k < lc; k++) {
        int pos = o + k;
        if (pos < MAXD) nbr[(size_t)i * MAXD + pos] = local[k];
    }
}

// ---------------- pack W_h [H,DIM,HIDD] -> [DIM, H*HIDD] ----------------
__global__ void packW_kernel(const float* __restrict__ W, float* __restrict__ Wp) {
    int idx = blockIdx.x * blockDim.x + threadIdx.x;
    if (idx >= DIM * NHEAD * HIDD) return;
    int k = idx / (NHEAD * HIDD);
    int c = idx % (NHEAD * HIDD);
    int h = c / HIDD, n = c % HIDD;
    Wp[idx] = W[(size_t)h * DIM * HIDD + (size_t)k * HIDD + n];
}

// ---------------- attention scalars: s1 = Wh@a[:F], s2 = Wh@a[F:] ----------------
__global__ void s12_kernel(const float* __restrict__ Wh, const float* __restrict__ a,
                           float* __restrict__ s1, float* __restrict__ s2, int Hn) {
    int warp = (blockIdx.x * blockDim.x + threadIdx.x) >> 5;
    int lane = threadIdx.x & 31;
    if (warp >= NNODES * Hn) return;
    int i = warp / Hn, h = warp % Hn;
    const float* w = Wh + (size_t)i * Hn * HIDD + (size_t)h * HIDD;
    const float* av = a + (size_t)h * 2 * HIDD;
    float a1 = 0.f, a2 = 0.f;
    for (int d = lane; d < HIDD; d += 32) {
        float x = w[d];
        a1 += x * av[d];
        a2 += x * av[HIDD + d];
    }
    for (int s = 16; s; s >>= 1) {
        a1 += __shfl_down_sync(0xffffffffu, a1, s);
        a2 += __shfl_down_sync(0xffffffffu, a2, s);
    }
    if (lane == 0) { s1[h * NNODES + i] = a1; s2[h * NNODES + i] = a2; }
}

// ---------------- sparse softmax-aggregate + ELU ----------------
__global__ void aggregate_kernel(const float* __restrict__ Wh,
                                 const int* __restrict__ nbr, const int* __restrict__ cnt,
                                 const float* __restrict__ s1, const float* __restrict__ s2,
                                 float* __restrict__ out, int Hn, int outStride, int outOff) {
    int b = blockIdx.x;
    int i = b / Hn, h = b % Hn;
    int t = threadIdx.x;  // 256 == HIDD
    __shared__ float w[MAXD];
    __shared__ float s_sum;
    int c = cnt[i];
    const int* nb = nbr + (size_t)i * MAXD;
    if (t < 32) {
        float m = -FLT_MAX;
        float base = s1[h * NNODES + i];
        for (int j = t; j < c; j += 32) {
            float e = base + s2[h * NNODES + nb[j]];
            e = e > 0.f ? e : 0.2f * e;  // leaky relu
            w[j] = e;
            m = fmaxf(m, e);
        }
        for (int s = 16; s; s >>= 1) m = fmaxf(m, __shfl_xor_sync(0xffffffffu, m, s));
        float sum = 0.f;
        for (int j = t; j < c; j += 32) {
            float ex = expf(w[j] - m);
            w[j] = ex;
            sum += ex;
        }
        for (int s = 16; s; s >>= 1) sum += __shfl_xor_sync(0xffffffffu, sum, s);
        if (t == 0) s_sum = sum;
    }
    __syncthreads();
    float acc = 0.f;
    for (int j = 0; j < c; j++)
        acc += w[j] * Wh[(size_t)nb[j] * (Hn * HIDD) + (size_t)h * HIDD + t];
    float v = acc / s_sum;
    v = v > 0.f ? v : expm1f(v);  // elu
    out[(size_t)i * outStride + outOff + (size_t)h * HIDD + t] = v;
}

// ---------------- final MLP layer (N=1) ----------------
__global__ void mlp3_kernel(const float* __restrict__ Xin, const float* __restrict__ W,
                            const float* __restrict__ b, float* __restrict__ out) {
    int warp = (blockIdx.x * blockDim.x + threadIdx.x) >> 5;
    int lane = threadIdx.x & 31;
    if (warp >= NNODES) return;
    float acc = 0.f;
    for (int d = lane; d < 128; d += 32) acc += Xin[(size_t)warp * 128 + d] * W[d];
    for (int s = 16; s; s >>= 1) acc += __shfl_down_sync(0xffffffffu, acc, s);
    if (lane == 0) out[warp] = acc + b[0];
}

// ---------------- host side ----------------
#define GETSYM(p, s)                               \
    do {                                           \
        void* _tmp = nullptr;                      \
        cudaGetSymbolAddress(&_tmp, s);            \
        p = (decltype(p))_tmp;                     \
    } while (0)

static void run_gat(const float* X, int mode, const float* W_h, const float* a_h,
                    const float* W_o, const float* a_o, int pairOff,
                    float* Xn, float* sq, float* sim, unsigned char* adj,
                    int* nbr, int* cnt, float* Wpack, float* Wh, float* s1, float* s2,
                    float* hidden, float* WhO, float* sO1, float* sO2, float* pair) {
    rowstat_kernel<<<NNODES, 256>>>(X, mode ? Xn : nullptr, sq);
    const float* Xs = mode ? Xn : X;
    gemm_k<128, 128, 8, 8, 8, true>
        <<<dim3(NNODES / 128, NNODES / 128), 256>>>(Xs, Xs, sim, NNODES, NNODES, DIM, nullptr, 0);
    clear_adj<<<1024, 256>>>(adj);
    topk_kernel<<<NNODES, 128>>>(sim, sq, adj, mode);
    build_nbr_kernel<<<NNODES, 256>>>(adj, nbr, cnt);
    packW_kernel<<<(DIM * NHEAD * HIDD + 255) / 256, 256>>>(W_h, Wpack);
    gemm_k<128, 128, 8, 8, 8, false>
        <<<dim3(NHEAD * HIDD / 128, NNODES / 128), 256>>>(X, Wpack, Wh, NNODES, NHEAD * HIDD, DIM,
                                                          nullptr, 0);
    s12_kernel<<<(NNODES * NHEAD) / 4, 128>>>(Wh, a_h, s1, s2, NHEAD);
    aggregate_kernel<<<NNODES * NHEAD, 256>>>(Wh, nbr, cnt, s1, s2, hidden, NHEAD, NHEAD * HIDD, 0);
    gemm_k<64, 64, 16, 4, 4, false>
        <<<dim3(HIDD / 64, NNODES / 64), 256>>>(hidden, W_o, WhO, NNODES, HIDD, NHEAD * HIDD,
                                                nullptr, 0);
    s12_kernel<<<NNODES / 4, 128>>>(WhO, a_o, sO1, sO2, 1);
    aggregate_kernel<<<NNODES, 256>>>(WhO, nbr, cnt, sO1, sO2, pair, 1, 2 * HIDD, pairOff);
}

extern "C" void kernel_launch(void* const* d_in, const int* in_sizes, int n_in,
                              void* d_out, int out_size) {
    const float* user_nodes = (const float*)d_in[0];
    const float* food_nodes = (const float*)d_in[1];
    const float* user_W_h = (const float*)d_in[2];
    const float* user_a_h = (const float*)d_in[3];
    const float* user_W_o = (const float*)d_in[4];
    const float* user_a_o = (const float*)d_in[5];
    const float* food_W_h = (const float*)d_in[6];
    const float* food_a_h = (const float*)d_in[7];
    const float* food_W_o = (const float*)d_in[8];
    const float* food_a_o = (const float*)d_in[9];
    const float* mlp_W0 = (const float*)d_in[10];
    const float* mlp_b0 = (const float*)d_in[11];
    const float* mlp_W1 = (const float*)d_in[12];
    const float* mlp_b1 = (const float*)d_in[13];
    const float* mlp_W2 = (const float*)d_in[14];
    const float* mlp_b2 = (const float*)d_in[15];
    const float* mlp_W3 = (const float*)d_in[16];
    const float* mlp_b3 = (const float*)d_in[17];

    float *Xn, *sq, *sim, *Wpack, *Wh, *s1, *s2, *hidden, *WhO, *sO1, *sO2, *pair, *m1, *m2, *m3;
    unsigned char* adj;
    int *nbr, *cnt;
    GETSYM(Xn, g_Xn);       GETSYM(sq, g_sq);      GETSYM(sim, g_sim);
    GETSYM(adj, g_adj);     GETSYM(nbr, g_nbr);    GETSYM(cnt, g_cnt);
    GETSYM(Wpack, g_Wpack); GETSYM(Wh, g_Wh);      GETSYM(s1, g_s1);
    GETSYM(s2, g_s2);       GETSYM(hidden, g_hidden); GETSYM(WhO, g_WhO);
    GETSYM(sO1, g_sO1);     GETSYM(sO2, g_sO2);    GETSYM(pair, g_pair);
    GETSYM(m1, g_m1);       GETSYM(m2, g_m2);      GETSYM(m3, g_m3);

    // user graph (euclid kNN) -> pair[:, 0:256]
    run_gat(user_nodes, 0, user_W_h, user_a_h, user_W_o, user_a_o, 0,
            Xn, sq, sim, adj, nbr, cnt, Wpack, Wh, s1, s2, hidden, WhO, sO1, sO2, pair);
    // food graph (cosine kNN) -> pair[:, 256:512]
    run_gat(food_nodes, 1, food_W_h, food_a_h, food_W_o, food_a_o, HIDD,
            Xn, sq, sim, adj, nbr, cnt, Wpack, Wh, s1, s2, hidden, WhO, sO1, sO2, pair);

    // MLP: 512 -> 512 -> 256 -> 128 -> 1
    gemm_k<64, 64, 16, 4, 4, false>
        <<<dim3(512 / 64, NNODES / 64), 256>>>(pair, mlp_W0, m1, NNODES, 512, 512, mlp_b0, 1);
    gemm_k<64, 64, 16, 4, 4, false>
        <<<dim3(256 / 64, NNODES / 64), 256>>>(m1, mlp_W1, m2, NNODES, 256, 512, mlp_b1, 1);
    gemm_k<64, 64, 16, 4, 4, false>
        <<<dim3(128 / 64, NNODES / 64), 256>>>(m2, mlp_W2, m3, NNODES, 128, 256, mlp_b2, 1);
    mlp3_kernel<<<NNODES / 4, 128>>>(m3, mlp_W3, mlp_b3, (float*)d_out);

    (void)in_sizes; (void)n_in; (void)out_size;
}

// round 2
// speedup vs baseline: 1.0522x; 1.0522x over previous
#include <cuda_runtime.h>
#include <float.h>
#include <math.h>

#define NNODES 2048
#define DIM    512
#define HIDD   256
#define NHEAD  4
#define TOPK   6
#define MAXD   256

// ---------------- scratch (device globals; no allocations allowed) ----------------
__device__ __align__(16) float g_Xn[NNODES * DIM];
__device__ __align__(16) float g_sq[NNODES];
__device__ __align__(16) float g_sim[NNODES * NNODES];
__device__ __align__(16) unsigned char g_adj[NNODES * NNODES];
__device__ int   g_nbr[NNODES * MAXD];
__device__ int   g_cnt[NNODES];
__device__ __align__(16) float g_Wpack[DIM * NHEAD * HIDD];
__device__ __align__(16) float g_Wh[NNODES * NHEAD * HIDD];
__device__ __align__(16) float g_s1[NHEAD * NNODES];
__device__ __align__(16) float g_s2[NHEAD * NNODES];
__device__ __align__(16) float g_hidden[NNODES * NHEAD * HIDD];
__device__ __align__(16) float g_WhO[NNODES * HIDD];
__device__ __align__(16) float g_sO1[NNODES];
__device__ __align__(16) float g_sO2[NNODES];
__device__ __align__(16) float g_pair[NNODES * 2 * HIDD];
__device__ __align__(16) float g_m1[NNODES * 512];
__device__ __align__(16) float g_m2[NNODES * 256];
__device__ __align__(16) float g_m3[NNODES * 128];

// ---------------- row norms ----------------
__global__ void rowstat_kernel(const float* __restrict__ X, float* __restrict__ Xn,
                               float* __restrict__ sq) {
    int i = blockIdx.x;
    int t = threadIdx.x;  // 256
    float s = 0.f;
    for (int d = t; d < DIM; d += 256) { float v = X[(size_t)i * DIM + d]; s += v * v; }
    __shared__ float sh[256];
    sh[t] = s; __syncthreads();
    for (int k = 128; k; k >>= 1) { if (t < k) sh[t] += sh[t + k]; __syncthreads(); }
    float tot = sh[0];
    if (t == 0) sq[i] = tot;
    if (Xn) {
        float inv = 1.0f / sqrtf(tot);
        for (int d = t; d < DIM; d += 256) Xn[(size_t)i * DIM + d] = X[(size_t)i * DIM + d] * inv;
    }
}

// ---------------- double-buffered tiled SGEMM ----------------
// C[M,Nc] = A[M,K] @ B ; if TB, B is [Nc,K] row-major (i.e. C = A @ B^T)
template <int BM, int BN, int BK, int TM, int TN, bool TB>
__global__ void __launch_bounds__((BM / TM) * (BN / TN))
gemm_db(const float* __restrict__ A, const float* __restrict__ B, float* __restrict__ C,
        int M, int Nc, int K, const float* __restrict__ bias, int relu) {
    constexpr int NT = (BM / TM) * (BN / TN);
    constexpr int KV = BK / 4;                       // float4s per k-column
    constexpr int LA = (BM * KV) / NT;               // A float4 loads / thread
    constexpr int NV = BN / 4;
    constexpr int LB = TB ? (BN * KV) / NT : (BK * NV) / NT;
    __shared__ __align__(16) float As[2][BK][BM];
    __shared__ __align__(16) float Bs[2][BK][BN];
    const int tid = threadIdx.x;
    const int row0 = blockIdx.y * BM;
    const int col0 = blockIdx.x * BN;
    const int tx = tid % (BN / TN);
    const int ty = tid / (BN / TN);

    float acc[TM][TN];
#pragma unroll
    for (int m = 0; m < TM; m++)
#pragma unroll
        for (int n = 0; n < TN; n++) acc[m][n] = 0.f;

    float4 ra[LA], rb[LB];

    auto fetchA = [&](int kk) {
#pragma unroll
        for (int l = 0; l < LA; l++) {
            int idx = tid + l * NT;
            int ar = idx / KV;
            int kc = (idx % KV) * 4;
            ra[l] = *(const float4*)(A + (size_t)(row0 + ar) * K + kk + kc);
        }
    };
    auto storeA = [&](int buf) {
#pragma unroll
        for (int l = 0; l < LA; l++) {
            int idx = tid + l * NT;
            int ar = idx / KV;
            int kc = (idx % KV) * 4;
            As[buf][kc + 0][ar] = ra[l].x; As[buf][kc + 1][ar] = ra[l].y;
            As[buf][kc + 2][ar] = ra[l].z; As[buf][kc + 3][ar] = ra[l].w;
        }
    };
    auto fetchB = [&](int kk) {
#pragma unroll
        for (int l = 0; l < LB; l++) {
            int idx = tid + l * NT;
            if (TB) {
                int bn = idx / KV;
                int kc = (idx % KV) * 4;
                rb[l] = *(const float4*)(B + (size_t)(col0 + bn) * K + kk + kc);
            } else {
                int br = idx / NV;
                int nc = (idx % NV) * 4;
                rb[l] = *(const float4*)(B + (size_t)(kk + br) * Nc + col0 + nc);
            }
        }
    };
    auto storeB = [&](int buf) {
#pragma unroll
        for (int l = 0; l < LB; l++) {
            int idx = tid + l * NT;
            if (TB) {
                int bn = idx / KV;
                int kc = (idx % KV) * 4;
                Bs[buf][kc + 0][bn] = rb[l].x; Bs[buf][kc + 1][bn] = rb[l].y;
                Bs[buf][kc + 2][bn] = rb[l].z; Bs[buf][kc + 3][bn] = rb[l].w;
            } else {
                int br = idx / NV;
                int nc = (idx % NV) * 4;
                *(float4*)&Bs[buf][br][nc] = rb[l];
            }
        }
    };

    const int ntiles = K / BK;
    fetchA(0); fetchB(0);
    storeA(0); storeB(0);
    __syncthreads();

    int cur = 0;
    for (int t = 0; t < ntiles; t++) {
        if (t + 1 < ntiles) { fetchA((t + 1) * BK); fetchB((t + 1) * BK); }
#pragma unroll
        for (int k = 0; k < BK; k++) {
            float ar[TM], br[TN];
#pragma unroll
            for (int m = 0; m < TM / 4; m++) {
                float4 v = *(const float4*)&As[cur][k][ty * TM + m * 4];
                ar[m * 4 + 0] = v.x; ar[m * 4 + 1] = v.y; ar[m * 4 + 2] = v.z; ar[m * 4 + 3] = v.w;
            }
#pragma unroll
            for (int n = 0; n < TN / 4; n++) {
                float4 v = *(const float4*)&Bs[cur][k][tx * TN + n * 4];
                br[n * 4 + 0] = v.x; br[n * 4 + 1] = v.y; br[n * 4 + 2] = v.z; br[n * 4 + 3] = v.w;
            }
#pragma unroll
            for (int m = 0; m < TM; m++)
#pragma unroll
                for (int n = 0; n < TN; n++) acc[m][n] += ar[m] * br[n];
        }
        if (t + 1 < ntiles) { storeA(cur ^ 1); storeB(cur ^ 1); }
        __syncthreads();
        cur ^= 1;
    }

#pragma unroll
    for (int m = 0; m < TM; m++) {
        int r = row0 + ty * TM + m;
#pragma unroll
        for (int n = 0; n < TN; n++) {
            int c = col0 + tx * TN + n;
            float v = acc[m][n];
            if (bias) v += bias[c];
            if (relu) v = fmaxf(v, 0.f);
            C[(size_t)r * Nc + c] = v;
        }
    }
}

// ---------------- clear adjacency ----------------
__global__ void clear_adj(unsigned char* adj) {
    int idx = blockIdx.x * blockDim.x + threadIdx.x;  // 262144 threads for 4MB
    ((int4*)adj)[idx] = make_int4(0, 0, 0, 0);
}

// ---------------- warp-per-row top-6 + edge writes ----------------
// mode 0: euclid — key = 2*dot - sq[j]; edge for any selected j != i
// mode 1: cosine — key = sim;           edge only if val > 0 and j != i
__device__ __forceinline__ bool tk_better(float v1, int i1, float v2, int i2) {
    return (v1 > v2) || (v1 == v2 && i1 < i2);
}
__global__ void topk_warp_kernel(const float* __restrict__ sim, const float* __restrict__ sq,
                                 unsigned char* __restrict__ adj, int mode) {
    int warp = (blockIdx.x * blockDim.x + threadIdx.x) >> 5;
    int lane = threadIdx.x & 31;
    if (warp >= NNODES) return;
    const int i = warp;
    float bv[TOPK]; int bi[TOPK];
#pragma unroll
    for (int k = 0; k < TOPK; k++) { bv[k] = -FLT_MAX; bi[k] = 0x7fffffff; }
    const float4* row = (const float4*)(sim + (size_t)i * NNODES);
    for (int c4 = lane; c4 < NNODES / 4; c4 += 32) {
        float4 v = row[c4];
        float e[4] = {v.x, v.y, v.z, v.w};
#pragma unroll
        for (int j = 0; j < 4; j++) {
            int c = c4 * 4 + j;
            float key = (mode == 0) ? (2.f * e[j] - sq[c]) : e[j];
            if (tk_better(key, c, bv[TOPK - 1], bi[TOPK - 1])) {
                bv[TOPK - 1] = key; bi[TOPK - 1] = c;
#pragma unroll
                for (int k = TOPK - 1; k > 0; k--) {
                    if (tk_better(bv[k], bi[k], bv[k - 1], bi[k - 1])) {
                        float tv = bv[k]; bv[k] = bv[k - 1]; bv[k - 1] = tv;
                        int ti = bi[k]; bi[k] = bi[k - 1]; bi[k - 1] = ti;
                    } else break;
                }
            }
        }
    }
    // warp-level 6-round selection (no syncthreads)
    float wv[TOPK]; int wi[TOPK];
    int p = 0;
#pragma unroll
    for (int r = 0; r < TOPK; r++) {
        float v = (p < TOPK) ? bv[p] : -FLT_MAX;
        int id = (p < TOPK) ? bi[p] : 0x7fffffff;
#pragma unroll
        for (int s = 16; s; s >>= 1) {
            float ov = __shfl_xor_sync(0xffffffffu, v, s);
            int oi = __shfl_xor_sync(0xffffffffu, id, s);
            if (tk_better(ov, oi, v, id)) { v = ov; id = oi; }
        }
        bool owner = (p < TOPK) && (bi[p] == id);
        if (owner) p++;
        wv[r] = v; wi[r] = id;
    }
    if (lane == 0) {
#pragma unroll
        for (int r = 0; r < TOPK; r++) {
            int j = wi[r];
            if (j == i) continue;
            if (mode == 1 && !(wv[r] > 0.f)) continue;
            adj[(size_t)i * NNODES + j] = 1;
            adj[(size_t)j * NNODES + i] = 1;
        }
    }
}

// ---------------- compact adjacency rows into neighbor lists ----------------
__global__ void build_nbr_kernel(const unsigned char* __restrict__ adj,
                                 int* __restrict__ nbr, int* __restrict__ cnt) {
    int i = blockIdx.x;
    int t = threadIdx.x;  // 256, each scans 8 contiguous columns
    int local[8]; int lc = 0;
    int base = t * 8;
#pragma unroll
    for (int k = 0; k < 8; k++) {
        int c = base + k;
        if (adj[(size_t)i * NNODES + c]) { local[lc++] = c; }
    }
    __shared__ int sh[256];
    __shared__ int off[256];
    sh[t] = lc; __syncthreads();
    if (t == 0) {
        int run = 0;
        for (int k = 0; k < 256; k++) { off[k] = run; run += sh[k]; }
        cnt[i] = run > MAXD ? MAXD : run;
    }
    __syncthreads();
    int o = off[t];
    for (int k = 0; k < lc; k++) {
        int pos = o + k;
        if (pos < MAXD) nbr[(size_t)i * MAXD + pos] = local[k];
    }
}

// ---------------- pack W_h [H,DIM,HIDD] -> [DIM, H*HIDD] ----------------
__global__ void packW_kernel(const float* __restrict__ W, float* __restrict__ Wp) {
    int idx = blockIdx.x * blockDim.x + threadIdx.x;
    if (idx >= DIM * NHEAD * HIDD) return;
    int k = idx / (NHEAD * HIDD);
    int c = idx % (NHEAD * HIDD);
    int h = c / HIDD, n = c % HIDD;
    Wp[idx] = W[(size_t)h * DIM * HIDD + (size_t)k * HIDD + n];
}

// ---------------- attention scalars: s1 = Wh@a[:F], s2 = Wh@a[F:] ----------------
__global__ void s12_kernel(const float* __restrict__ Wh, const float* __restrict__ a,
                           float* __restrict__ s1, float* __restrict__ s2, int Hn) {
    int warp = (blockIdx.x * blockDim.x + threadIdx.x) >> 5;
    int lane = threadIdx.x & 31;
    if (warp >= NNODES * Hn) return;
    int i = warp / Hn, h = warp % Hn;
    const float* w = Wh + (size_t)i * Hn * HIDD + (size_t)h * HIDD;
    const float* av = a + (size_t)h * 2 * HIDD;
    float a1 = 0.f, a2 = 0.f;
    for (int d = lane; d < HIDD; d += 32) {
        float x = w[d];
        a1 += x * av[d];
        a2 += x * av[HIDD + d];
    }
    for (int s = 16; s; s >>= 1) {
        a1 += __shfl_down_sync(0xffffffffu, a1, s);
        a2 += __shfl_down_sync(0xffffffffu, a2, s);
    }
    if (lane == 0) { s1[h * NNODES + i] = a1; s2[h * NNODES + i] = a2; }
}

// ---------------- sparse softmax-aggregate + ELU ----------------
__global__ void aggregate_kernel(const float* __restrict__ Wh,
                                 const int* __restrict__ nbr, const int* __restrict__ cnt,
                                 const float* __restrict__ s1, const float* __restrict__ s2,
                                 float* __restrict__ out, int Hn, int outStride, int outOff) {
    int b = blockIdx.x;
    int i = b / Hn, h = b % Hn;
    int t = threadIdx.x;  // 256 == HIDD
    __shared__ float w[MAXD];
    __shared__ float s_sum;
    int c = cnt[i];
    const int* nb = nbr + (size_t)i * MAXD;
    if (t < 32) {
        float m = -FLT_MAX;
        float base = s1[h * NNODES + i];
        for (int j = t; j < c; j += 32) {
            float e = base + s2[h * NNODES + nb[j]];
            e = e > 0.f ? e : 0.2f * e;  // leaky relu
            w[j] = e;
            m = fmaxf(m, e);
        }
        for (int s = 16; s; s >>= 1) m = fmaxf(m, __shfl_xor_sync(0xffffffffu, m, s));
        float sum = 0.f;
        for (int j = t; j < c; j += 32) {
            float ex = expf(w[j] - m);
            w[j] = ex;
            sum += ex;
        }
        for (int s = 16; s; s >>= 1) sum += __shfl_xor_sync(0xffffffffu, sum, s);
        if (t == 0) s_sum = sum;
    }
    __syncthreads();
    float acc = 0.f;
    for (int j = 0; j < c; j++)
        acc += w[j] * Wh[(size_t)nb[j] * (Hn * HIDD) + (size_t)h * HIDD + t];
    float v = acc / s_sum;
    v = v > 0.f ? v : expm1f(v);  // elu
    out[(size_t)i * outStride + outOff + (size_t)h * HIDD + t] = v;
}

// ---------------- final MLP layer (N=1) ----------------
__global__ void mlp3_kernel(const float* __restrict__ Xin, const float* __restrict__ W,
                            const float* __restrict__ b, float* __restrict__ out) {
    int warp = (blockIdx.x * blockDim.x + threadIdx.x) >> 5;
    int lane = threadIdx.x & 31;
    if (warp >= NNODES) return;
    float acc = 0.f;
    for (int d = lane; d < 128; d += 32) acc += Xin[(size_t)warp * 128 + d] * W[d];
    for (int s = 16; s; s >>= 1) acc += __shfl_down_sync(0xffffffffu, acc, s);
    if (lane == 0) out[warp] = acc + b[0];
}

// ---------------- host side ----------------
#define GETSYM(p, s)                               \
    do {                                           \
        void* _tmp = nullptr;                      \
        cudaGetSymbolAddress(&_tmp, s);            \
        p = (decltype(p))_tmp;                     \
    } while (0)

static void run_gat(const float* X, int mode, const float* W_h, const float* a_h,
                    const float* W_o, const float* a_o, int pairOff,
                    float* Xn, float* sq, float* sim, unsigned char* adj,
                    int* nbr, int* cnt, float* Wpack, float* Wh, float* s1, float* s2,
                    float* hidden, float* WhO, float* sO1, float* sO2, float* pair) {
    rowstat_kernel<<<NNODES, 256>>>(X, mode ? Xn : nullptr, sq);
    const float* Xs = mode ? Xn : X;
    gemm_db<128, 128, 16, 8, 8, true>
        <<<dim3(NNODES / 128, NNODES / 128), 256>>>(Xs, Xs, sim, NNODES, NNODES, DIM, nullptr, 0);
    clear_adj<<<1024, 256>>>(adj);
    topk_warp_kernel<<<NNODES / 8, 256>>>(sim, sq, adj, mode);
    build_nbr_kernel<<<NNODES, 256>>>(adj, nbr, cnt);
    packW_kernel<<<(DIM * NHEAD * HIDD + 255) / 256, 256>>>(W_h, Wpack);
    gemm_db<128, 64, 16, 8, 4, false>
        <<<dim3(NHEAD * HIDD / 64, NNODES / 128), 256>>>(X, Wpack, Wh, NNODES, NHEAD * HIDD, DIM,
                                                         nullptr, 0);
    s12_kernel<<<(NNODES * NHEAD) / 4, 128>>>(Wh, a_h, s1, s2, NHEAD);
    aggregate_kernel<<<NNODES * NHEAD, 256>>>(Wh, nbr, cnt, s1, s2, hidden, NHEAD, NHEAD * HIDD, 0);
    gemm_db<64, 64, 16, 4, 4, false>
        <<<dim3(HIDD / 64, NNODES / 64), 256>>>(hidden, W_o, WhO, NNODES, HIDD, NHEAD * HIDD,
                                                nullptr, 0);
    s12_kernel<<<NNODES / 4, 128>>>(WhO, a_o, sO1, sO2, 1);
    aggregate_kernel<<<NNODES, 256>>>(WhO, nbr, cnt, sO1, sO2, pair, 1, 2 * HIDD, pairOff);
}

extern "C" void kernel_launch(void* const* d_in, const int* in_sizes, int n_in,
                              void* d_out, int out_size) {
    const float* user_nodes = (const float*)d_in[0];
    const float* food_nodes = (const float*)d_in[1];
    const float* user_W_h = (const float*)d_in[2];
    const float* user_a_h = (const float*)d_in[3];
    const float* user_W_o = (const float*)d_in[4];
    const float* user_a_o = (const float*)d_in[5];
    const float* food_W_h = (const float*)d_in[6];
    const float* food_a_h = (const float*)d_in[7];
    const float* food_W_o = (const float*)d_in[8];
    const float* food_a_o = (const float*)d_in[9];
    const float* mlp_W0 = (const float*)d_in[10];
    const float* mlp_b0 = (const float*)d_in[11];
    const float* mlp_W1 = (const float*)d_in[12];
    const float* mlp_b1 = (const float*)d_in[13];
    const float* mlp_W2 = (const float*)d_in[14];
    const float* mlp_b2 = (const float*)d_in[15];
    const float* mlp_W3 = (const float*)d_in[16];
    const float* mlp_b3 = (const float*)d_in[17];

    float *Xn, *sq, *sim, *Wpack, *Wh, *s1, *s2, *hidden, *WhO, *sO1, *sO2, *pair, *m1, *m2, *m3;
    unsigned char* adj;
    int *nbr, *cnt;
    GETSYM(Xn, g_Xn);       GETSYM(sq, g_sq);      GETSYM(sim, g_sim);
    GETSYM(adj, g_adj);     GETSYM(nbr, g_nbr);    GETSYM(cnt, g_cnt);
    GETSYM(Wpack, g_Wpack); GETSYM(Wh, g_Wh);      GETSYM(s1, g_s1);
    GETSYM(s2, g_s2);       GETSYM(hidden, g_hidden); GETSYM(WhO, g_WhO);
    GETSYM(sO1, g_sO1);     GETSYM(sO2, g_sO2);    GETSYM(pair, g_pair);
    GETSYM(m1, g_m1);       GETSYM(m2, g_m2);      GETSYM(m3, g_m3);

    // user graph (euclid kNN) -> pair[:, 0:256]
    run_gat(user_nodes, 0, user_W_h, user_a_h, user_W_o, user_a_o, 0,
            Xn, sq, sim, adj, nbr, cnt, Wpack, Wh, s1, s2, hidden, WhO, sO1, sO2, pair);
    // food graph (cosine kNN) -> pair[:, 256:512]
    run_gat(food_nodes, 1, food_W_h, food_a_h, food_W_o, food_a_o, HIDD,
            Xn, sq, sim, adj, nbr, cnt, Wpack, Wh, s1, s2, hidden, WhO, sO1, sO2, pair);

    // MLP: 512 -> 512 -> 256 -> 128 -> 1
    gemm_db<64, 64, 16, 4, 4, false>
        <<<dim3(512 / 64, NNODES / 64), 256>>>(pair, mlp_W0, m1, NNODES, 512, 512, mlp_b0, 1);
    gemm_db<64, 64, 16, 4, 4, false>
        <<<dim3(256 / 64, NNODES / 64), 256>>>(m1, mlp_W1, m2, NNODES, 256, 512, mlp_b1, 1);
    gemm_db<64, 64, 16, 4, 4, false>
        <<<dim3(128 / 64, NNODES / 64), 256>>>(m2, mlp_W2, m3, NNODES, 128, 256, mlp_b2, 1);
    mlp3_kernel<<<NNODES / 4, 128>>>(m3, mlp_W3, mlp_b3, (float*)d_out);

    (void)in_sizes; (void)n_in; (void)out_size;
}

// round 7
// speedup vs baseline: 1.6456x; 1.5639x over previous
#include <cuda_runtime.h>
#include <cuda_bf16.h>
#include <float.h>
#include <math.h>
#include <cstdint>

#define NNODES 2048
#define DIM    512
#define HIDD   256
#define NHEAD  4
#define TOPK   6
#define MAXD   256

// ================= scratch (device globals) =================
__device__ __align__(16) float g_Xn[NNODES * DIM];
__device__ __align__(16) float g_sq[NNODES];
__device__ __align__(16) float g_sim[NNODES * NNODES];
__device__ __align__(16) __nv_bfloat16 g_Ap[NNODES * 3 * 1024];   // activation pack (up to K=1024)
__device__ __align__(16) __nv_bfloat16 g_Bp[NNODES * 3 * DIM];    // sim B-side pack
__device__ __align__(16) __nv_bfloat16 g_Wp[1024 * 3 * 1024];     // weight packs
__device__ unsigned g_bits[NNODES * 64];
__device__ int   g_nbr[NNODES * MAXD];
__device__ int   g_cnt[NNODES];
__device__ __align__(16) float g_Wh[NNODES * NHEAD * HIDD];
__device__ __align__(16) float g_s1[NHEAD * NNODES];
__device__ __align__(16) float g_s2[NHEAD * NNODES];
__device__ __align__(16) float g_hidden[NNODES * NHEAD * HIDD];
__device__ __align__(16) float g_WhO[NNODES * HIDD];
__device__ __align__(16) float g_sO1[NNODES];
__device__ __align__(16) float g_sO2[NNODES];
__device__ __align__(16) float g_pair[NNODES * 2 * HIDD];
__device__ __align__(16) float g_m1[NNODES * 512];
__device__ __align__(16) float g_m2[NNODES * 256];
__device__ __align__(16) float g_m3[NNODES * 128];

// ================= small PTX helpers =================
__device__ __forceinline__ uint32_t smem_to_u32(const void* p) {
    uint32_t a;
    asm("{ .reg .u64 t; cvta.to.shared.u64 t, %1; cvt.u32.u64 %0, t; }" : "=r"(a) : "l"(p));
    return a;
}
__device__ __forceinline__ void cp_async16(uint32_t saddr, const void* gaddr) {
    asm volatile("cp.async.cg.shared.global [%0], [%1], 16;" :: "r"(saddr), "l"(gaddr));
}
__device__ __forceinline__ void cp_commit() { asm volatile("cp.async.commit_group;"); }
template <int N>
__device__ __forceinline__ void cp_wait() { asm volatile("cp.async.wait_group %0;" :: "n"(N)); }

__device__ __forceinline__ void ldmatrix_x4(uint32_t* r, uint32_t addr) {
    asm volatile("ldmatrix.sync.aligned.m8n8.x4.shared.b16 {%0,%1,%2,%3}, [%4];"
                 : "=r"(r[0]), "=r"(r[1]), "=r"(r[2]), "=r"(r[3]) : "r"(addr));
}
__device__ __forceinline__ void ldmatrix_x2(uint32_t* r, uint32_t addr) {
    asm volatile("ldmatrix.sync.aligned.m8n8.x2.shared.b16 {%0,%1}, [%2];"
                 : "=r"(r[0]), "=r"(r[1]) : "r"(addr));
}
__device__ __forceinline__ void mma16816(float* c, const uint32_t* a, const uint32_t* b) {
    asm volatile(
        "mma.sync.aligned.m16n8k16.row.col.f32.bf16.bf16.f32 "
        "{%0,%1,%2,%3}, {%4,%5,%6,%7}, {%8,%9}, {%0,%1,%2,%3};"
        : "+f"(c[0]), "+f"(c[1]), "+f"(c[2]), "+f"(c[3])
        : "r"(a[0]), "r"(a[1]), "r"(a[2]), "r"(a[3]), "r"(b[0]), "r"(b[1]));
}

// ================= row norms =================
__global__ void rowstat_kernel(const float* __restrict__ X, float* __restrict__ Xn,
                               float* __restrict__ sq) {
    int i = blockIdx.x;
    int t = threadIdx.x;  // 256
    float s = 0.f;
    for (int d = t; d < DIM; d += 256) { float v = X[(size_t)i * DIM + d]; s += v * v; }
    __shared__ float sh[256];
    sh[t] = s; __syncthreads();
    for (int k = 128; k; k >>= 1) { if (t < k) sh[t] += sh[t + k]; __syncthreads(); }
    float tot = sh[0];
    if (t == 0) sq[i] = tot;
    if (Xn) {
        float inv = 1.0f / sqrtf(tot);
        for (int d = t; d < DIM; d += 256) Xn[(size_t)i * DIM + d] = X[(size_t)i * DIM + d] * inv;
    }
}

// ================= packing: fp32 [M,K] -> bf16 [M,3K] =================
// pat 0 (A side): [hi | hi | lo] ; pat 1 (B side): [hi | lo | hi]
__global__ void pack3_kernel(const float* __restrict__ src, __nv_bfloat16* __restrict__ dst,
                             int K, int total, int pat) {
    int idx = blockIdx.x * blockDim.x + threadIdx.x;
    if (idx >= total) return;
    int row = idx / K, col = idx % K;
    float x = src[idx];
    __nv_bfloat16 hi = __float2bfloat16(x);
    __nv_bfloat16 lo = __float2bfloat16(x - __bfloat162float(hi));
    size_t base = (size_t)row * 3 * K + col;
    dst[base] = hi;
    dst[base + K] = pat ? lo : hi;
    dst[base + 2 * K] = pat ? hi : lo;
}

// W_h [H, DIM, HIDD] -> [H*HIDD, 3*DIM] pat B
__global__ void packWh3_kernel(const float* __restrict__ W, __nv_bfloat16* __restrict__ dst) {
    int idx = blockIdx.x * blockDim.x + threadIdx.x;
    if (idx >= NHEAD * HIDD * DIM) return;
    int n = idx / DIM, k = idx % DIM;
    int h = n / HIDD, hid = n % HIDD;
    float w = W[(size_t)h * DIM * HIDD + (size_t)k * HIDD + hid];
    __nv_bfloat16 hi = __float2bfloat16(w);
    __nv_bfloat16 lo = __float2bfloat16(w - __bfloat162float(hi));
    size_t base = (size_t)n * 3 * DIM + k;
    dst[base] = hi; dst[base + DIM] = lo; dst[base + 2 * DIM] = hi;
}

// generic weight W [K, N] -> [N, 3K] pat B
__global__ void packWgen3_kernel(const float* __restrict__ W, __nv_bfloat16* __restrict__ dst,
                                 int K, int N) {
    int idx = blockIdx.x * blockDim.x + threadIdx.x;
    if (idx >= N * K) return;
    int n = idx / K, k = idx % K;
    float w = W[(size_t)k * N + n];
    __nv_bfloat16 hi = __float2bfloat16(w);
    __nv_bfloat16 lo = __float2bfloat16(w - __bfloat162float(hi));
    size_t base = (size_t)n * 3 * K + k;
    dst[base] = hi; dst[base + K] = lo; dst[base + 2 * K] = hi;
}

// ================= mma.sync bf16 GEMM: C[M,Nc] = A[M,K] @ B[Nc,K]^T =================
// 128x128 tile, BK=64 bf16 (128B rows, SW128 swizzle), cp.async double buffer.
// 8 warps as 2x4 -> 64x32 warp tile, m16n8k16.
#define MMA_SMEM_BYTES 65536

__global__ void __launch_bounds__(256, 2)
mma_gemm(const __nv_bfloat16* __restrict__ A, const __nv_bfloat16* __restrict__ B,
         float* __restrict__ C, int Nc, int K, const float* __restrict__ bias, int relu) {
    extern __shared__ char sm[];
    const int tid = threadIdx.x;
    const int lane = tid & 31;
    const int warp = tid >> 5;
    const int wm = warp >> 2;   // 0..1
    const int wn = warp & 3;    // 0..3
    const int row0 = blockIdx.y * 128;
    const int col0 = blockIdx.x * 128;
    const uint32_t sbase = smem_to_u32(sm);

    const __nv_bfloat16* Aptr = A + (size_t)row0 * K;
    const __nv_bfloat16* Bptr = B + (size_t)col0 * K;

    float acc[4][4][4];
#pragma unroll
    for (int mt = 0; mt < 4; mt++)
#pragma unroll
        for (int nt = 0; nt < 4; nt++)
#pragma unroll
            for (int q = 0; q < 4; q++) acc[mt][nt][q] = 0.f;

    // per-thread fixed load slots: 1024 uint4 per 16KB tile / 256 threads = 4 each
    const int nch = K / 64;
    auto issue = [&](int c) {
        uint32_t base = sbase + (c & 1) * 32768;
        int koff = c * 64;
#pragma unroll
        for (int l = 0; l < 4; l++) {
            int idx = tid + l * 256;
            int r = idx >> 3;
            int jb = (idx & 7) * 16;
            unsigned off = r * 128 + jb;
            unsigned sw = off ^ ((off >> 3) & 0x70);
            cp_async16(base + sw, (const char*)(Aptr + (size_t)r * K + koff) + jb);
            cp_async16(base + 16384 + sw, (const char*)(Bptr + (size_t)r * K + koff) + jb);
        }
        cp_commit();
    };

    issue(0);
    for (int c = 0; c < nch; c++) {
        if (c + 1 < nch) { issue(c + 1); cp_wait<1>(); }
        else cp_wait<0>();
        __syncthreads();
        uint32_t aBase = sbase + (c & 1) * 32768;
        uint32_t bBase = aBase + 16384;
#pragma unroll
        for (int ks = 0; ks < 4; ks++) {
            uint32_t af[4][4], bf[4][2];
#pragma unroll
            for (int mt = 0; mt < 4; mt++) {
                int r = wm * 64 + mt * 16 + (lane & 15);
                unsigned off = r * 128 + ks * 32 + (lane >> 4) * 16;
                unsigned sw = off ^ ((off >> 3) & 0x70);
                ldmatrix_x4(af[mt], aBase + sw);
            }
#pragma unroll
            for (int nt = 0; nt < 4; nt++) {
                int r = wn * 32 + nt * 8 + (lane & 7);
                unsigned off = r * 128 + ks * 32 + ((lane >> 3) & 1) * 16;
                unsigned sw = off ^ ((off >> 3) & 0x70);
                ldmatrix_x2(bf[nt], bBase + sw);
            }
#pragma unroll
            for (int mt = 0; mt < 4; mt++)
#pragma unroll
                for (int nt = 0; nt < 4; nt++)
                    mma16816(acc[mt][nt], af[mt], bf[nt]);
        }
        __syncthreads();
    }

#pragma unroll
    for (int mt = 0; mt < 4; mt++) {
        int r0 = row0 + wm * 64 + mt * 16 + (lane >> 2);
#pragma unroll
        for (int nt = 0; nt < 4; nt++) {
            int cc = col0 + wn * 32 + nt * 8 + (lane & 3) * 2;
            float b0 = 0.f, b1 = 0.f;
            if (bias) { b0 = bias[cc]; b1 = bias[cc + 1]; }
            float v0 = acc[mt][nt][0] + b0, v1 = acc[mt][nt][1] + b1;
            float v2 = acc[mt][nt][2] + b0, v3 = acc[mt][nt][3] + b1;
            if (relu) {
                v0 = fmaxf(v0, 0.f); v1 = fmaxf(v1, 0.f);
                v2 = fmaxf(v2, 0.f); v3 = fmaxf(v3, 0.f);
            }
            *(float2*)(C + (size_t)r0 * Nc + cc) = make_float2(v0, v1);
            *(float2*)(C + (size_t)(r0 + 8) * Nc + cc) = make_float2(v2, v3);
        }
    }
}

// ================= top-6: 4 warps per row + merge, edges into bitmask =================
__device__ __forceinline__ bool tk_better(float v1, int i1, float v2, int i2) {
    return (v1 > v2) || (v1 == v2 && i1 < i2);
}
__global__ void topk_kernel2(const float* __restrict__ sim, const float* __restrict__ sq,
                             unsigned* __restrict__ bits, int mode) {
    const int i = blockIdx.x;
    const int t = threadIdx.x;  // 128
    const int w = t >> 5, lane = t & 31;
    float bv[TOPK]; int bi[TOPK];
#pragma unroll
    for (int k = 0; k < TOPK; k++) { bv[k] = -FLT_MAX; bi[k] = 0x7fffffff; }
    const float4* row = (const float4*)(sim + (size_t)i * NNODES);
#pragma unroll
    for (int it = 0; it < 4; it++) {
        int c4 = w * 128 + it * 32 + lane;
        float4 v = row[c4];
        float e[4] = {v.x, v.y, v.z, v.w};
#pragma unroll
        for (int j = 0; j < 4; j++) {
            int c = c4 * 4 + j;
            float key = (mode == 0) ? (2.f * e[j] - sq[c]) : e[j];
            if (tk_better(key, c, bv[TOPK - 1], bi[TOPK - 1])) {
                bv[TOPK - 1] = key; bi[TOPK - 1] = c;
#pragma unroll
                for (int k = TOPK - 1; k > 0; k--) {
                    if (tk_better(bv[k], bi[k], bv[k - 1], bi[k - 1])) {
                        float tv = bv[k]; bv[k] = bv[k - 1]; bv[k - 1] = tv;
                        int ti = bi[k]; bi[k] = bi[k - 1]; bi[k - 1] = ti;
                    } else break;
                }
            }
        }
    }
    __shared__ float sv[4 * TOPK];
    __shared__ int si[4 * TOPK];
    {
        int p = 0;
#pragma unroll
        for (int r = 0; r < TOPK; r++) {
            float v = (p < TOPK) ? bv[p] : -FLT_MAX;
            int id = (p < TOPK) ? bi[p] : 0x7fffffff;
#pragma unroll
            for (int s = 16; s; s >>= 1) {
                float ov = __shfl_xor_sync(0xffffffffu, v, s);
                int oi = __shfl_xor_sync(0xffffffffu, id, s);
                if (tk_better(ov, oi, v, id)) { v = ov; id = oi; }
            }
            if (p < TOPK && bi[p] == id) p++;
            if (lane == 0) { sv[w * TOPK + r] = v; si[w * TOPK + r] = id; }
        }
    }
    __syncthreads();
    if (w == 0) {
        float v = (lane < 4 * TOPK) ? sv[lane] : -FLT_MAX;
        int id = (lane < 4 * TOPK) ? si[lane] : 0x7fffffff;
#pragma unroll
        for (int r = 0; r < TOPK; r++) {
            float mv = v; int mi = id;
#pragma unroll
            for (int s = 16; s; s >>= 1) {
                float ov = __shfl_xor_sync(0xffffffffu, mv, s);
                int oi = __shfl_xor_sync(0xffffffffu, mi, s);
                if (tk_better(ov, oi, mv, mi)) { mv = ov; mi = oi; }
            }
            if (id == mi) { v = -FLT_MAX; id = 0x7fffffff; }
            if (lane == 0 && mi < NNODES) {
                int j = mi;
                bool ok = (j != i) && (mode == 0 || mv > 0.f);
                if (ok) {
                    atomicOr(&bits[(size_t)i * 64 + (j >> 5)], 1u << (j & 31));
                    atomicOr(&bits[(size_t)j * 64 + (i >> 5)], 1u << (i & 31));
                }
            }
        }
    }
}

// ================= neighbor lists from bitmask (warp per row) =================
__global__ void build_nbr_bits(const unsigned* __restrict__ bits, int* __restrict__ nbr,
                               int* __restrict__ cnt) {
    int warp = (blockIdx.x * blockDim.x + threadIdx.x) >> 5;
    int lane = threadIdx.x & 31;
    if (warp >= NNODES) return;
    const int i = warp;
    unsigned w0 = bits[(size_t)i * 64 + 2 * lane];
    unsigned w1 = bits[(size_t)i * 64 + 2 * lane + 1];
    int c = __popc(w0) + __popc(w1);
    int off = c;
#pragma unroll
    for (int s = 1; s < 32; s <<= 1) {
        int v = __shfl_up_sync(0xffffffffu, off, s);
        if (lane >= s) off += v;
    }
    int total = __shfl_sync(0xffffffffu, off, 31);
    off -= c;
    if (lane == 0) cnt[i] = total > MAXD ? MAXD : total;
    int base = lane * 64;
    int pos = off;
    while (w0) {
        int b = __ffs(w0) - 1; w0 &= w0 - 1;
        if (pos < MAXD) nbr[(size_t)i * MAXD + pos] = base + b;
        pos++;
    }
    base += 32;
    while (w1) {
        int b = __ffs(w1) - 1; w1 &= w1 - 1;
        if (pos < MAXD) nbr[(size_t)i * MAXD + pos] = base + b;
        pos++;
    }
}

// ================= attention scalars =================
__global__ void s12_kernel(const float* __restrict__ Wh, const float* __restrict__ a,
                           float* __restrict__ s1, float* __restrict__ s2, int Hn) {
    int warp = (blockIdx.x * blockDim.x + threadIdx.x) >> 5;
    int lane = threadIdx.x & 31;
    if (warp >= NNODES * Hn) return;
    int i = warp / Hn, h = warp % Hn;
    const float* w = Wh + (size_t)i * Hn * HIDD + (size_t)h * HIDD;
    const float* av = a + (size_t)h * 2 * HIDD;
    float a1 = 0.f, a2 = 0.f;
    for (int d = lane; d < HIDD; d += 32) {
        float x = w[d];
        a1 += x * av[d];
        a2 += x * av[HIDD + d];
    }
    for (int s = 16; s; s >>= 1) {
        a1 += __shfl_down_sync(0xffffffffu, a1, s);
        a2 += __shfl_down_sync(0xffffffffu, a2, s);
    }
    if (lane == 0) { s1[h * NNODES + i] = a1; s2[h * NNODES + i] = a2; }
}

// ================= sparse softmax-aggregate + ELU =================
__global__ void aggregate_kernel(const float* __restrict__ Wh,
                                 const int* __restrict__ nbr, const int* __restrict__ cnt,
                                 const float* __restrict__ s1, const float* __restrict__ s2,
                                 float* __restrict__ out, int Hn, int outStride, int outOff) {
    int b = blockIdx.x;
    int i = b / Hn, h = b % Hn;
    int t = threadIdx.x;  // 256 == HIDD
    __shared__ float w[MAXD];
    __shared__ float s_sum;
    int c = cnt[i];
    const int* nb = nbr + (size_t)i * MAXD;
    if (t < 32) {
        float m = -FLT_MAX;
        float base = s1[h * NNODES + i];
        for (int j = t; j < c; j += 32) {
            float e = base + s2[h * NNODES + nb[j]];
            e = e > 0.f ? e : 0.2f * e;  // leaky relu
            w[j] = e;
            m = fmaxf(m, e);
        }
        for (int s = 16; s; s >>= 1) m = fmaxf(m, __shfl_xor_sync(0xffffffffu, m, s));
        float sum = 0.f;
        for (int j = t; j < c; j += 32) {
            float ex = expf(w[j] - m);
            w[j] = ex;
            sum += ex;
        }
        for (int s = 16; s; s >>= 1) sum += __shfl_xor_sync(0xffffffffu, sum, s);
        if (t == 0) s_sum = sum;
    }
    __syncthreads();
    float acc = 0.f;
    for (int j = 0; j < c; j++)
        acc += w[j] * Wh[(size_t)nb[j] * (Hn * HIDD) + (size_t)h * HIDD + t];
    float v = acc / s_sum;
    v = v > 0.f ? v : expm1f(v);  // elu
    out[(size_t)i * outStride + outOff + (size_t)h * HIDD + t] = v;
}

// ================= final MLP layer (N=1) =================
__global__ void mlp3_kernel(const float* __restrict__ Xin, const float* __restrict__ W,
                            const float* __restrict__ b, float* __restrict__ out) {
    int warp = (blockIdx.x * blockDim.x + threadIdx.x) >> 5;
    int lane = threadIdx.x & 31;
    if (warp >= NNODES) return;
    float acc = 0.f;
    for (int d = lane; d < 128; d += 32) acc += Xin[(size_t)warp * 128 + d] * W[d];
    for (int s = 16; s; s >>= 1) acc += __shfl_down_sync(0xffffffffu, acc, s);
    if (lane == 0) out[warp] = acc + b[0];
}

// ================= host side =================
#define GETSYM(p, s)                               \
    do {                                           \
        void* _tmp = nullptr;                      \
        cudaGetSymbolAddress(&_tmp, s);            \
        p = (decltype(p))_tmp;                     \
    } while (0)

struct Ctx {
    float *Xn, *sq, *sim, *Wh, *s1, *s2, *hidden, *WhO, *sO1, *sO2, *pair, *m1, *m2, *m3;
    __nv_bfloat16 *Ap, *Bp, *Wp;
    unsigned* bits;
    int *nbr, *cnt;
};

static inline void launch_mma(const __nv_bfloat16* A, const __nv_bfloat16* B, float* C,
                              int M, int Nc, int Kp, const float* bias, int relu) {
    mma_gemm<<<dim3(Nc / 128, M / 128), 256, MMA_SMEM_BYTES>>>(A, B, C, Nc, Kp, bias, relu);
}

static void run_gat(const Ctx& c, const float* X, int mode, const float* W_h, const float* a_h,
                    const float* W_o, const float* a_o, int pairOff) {
    rowstat_kernel<<<NNODES, 256>>>(X, mode ? c.Xn : nullptr, c.sq);
    const float* Xs = mode ? c.Xn : X;
    // sim = Xs @ Xs^T via split-bf16 mma
    pack3_kernel<<<(NNODES * DIM + 255) / 256, 256>>>(Xs, c.Ap, DIM, NNODES * DIM, 0);
    pack3_kernel<<<(NNODES * DIM + 255) / 256, 256>>>(Xs, c.Bp, DIM, NNODES * DIM, 1);
    launch_mma(c.Ap, c.Bp, c.sim, NNODES, NNODES, 3 * DIM, nullptr, 0);
    cudaMemsetAsync(c.bits, 0, (size_t)NNODES * 64 * sizeof(unsigned));
    topk_kernel2<<<NNODES, 128>>>(c.sim, c.sq, c.bits, mode);
    build_nbr_bits<<<NNODES / 8, 256>>>(c.bits, c.nbr, c.cnt);
    // Wh = X @ W_h(packed)  [uses raw X even in cosine mode]
    if (mode) pack3_kernel<<<(NNODES * DIM + 255) / 256, 256>>>(X, c.Ap, DIM, NNODES * DIM, 0);
    packWh3_kernel<<<(NHEAD * HIDD * DIM + 255) / 256, 256>>>(W_h, c.Wp);
    launch_mma(c.Ap, c.Wp, c.Wh, NNODES, NHEAD * HIDD, 3 * DIM, nullptr, 0);
    s12_kernel<<<(NNODES * NHEAD) / 4, 128>>>(c.Wh, a_h, c.s1, c.s2, NHEAD);
    aggregate_kernel<<<NNODES * NHEAD, 256>>>(c.Wh, c.nbr, c.cnt, c.s1, c.s2, c.hidden, NHEAD,
                                              NHEAD * HIDD, 0);
    // WhO = hidden @ W_o
    pack3_kernel<<<(NNODES * 1024 + 255) / 256, 256>>>(c.hidden, c.Ap, 1024, NNODES * 1024, 0);
    packWgen3_kernel<<<(1024 * HIDD + 255) / 256, 256>>>(W_o, c.Wp, 1024, HIDD);
    launch_mma(c.Ap, c.Wp, c.WhO, NNODES, HIDD, 3 * 1024, nullptr, 0);
    s12_kernel<<<NNODES / 4, 128>>>(c.WhO, a_o, c.sO1, c.sO2, 1);
    aggregate_kernel<<<NNODES, 256>>>(c.WhO, c.nbr, c.cnt, c.sO1, c.sO2, c.pair, 1, 2 * HIDD,
                                      pairOff);
}

extern "C" void kernel_launch(void* const* d_in, const int* in_sizes, int n_in,
                              void* d_out, int out_size) {
    const float* user_nodes = (const float*)d_in[0];
    const float* food_nodes = (const float*)d_in[1];
    const float* user_W_h = (const float*)d_in[2];
    const float* user_a_h = (const float*)d_in[3];
    const float* user_W_o = (const float*)d_in[4];
    const float* user_a_o = (const float*)d_in[5];
    const float* food_W_h = (const float*)d_in[6];
    const float* food_a_h = (const float*)d_in[7];
    const float* food_W_o = (const float*)d_in[8];
    const float* food_a_o = (const float*)d_in[9];
    const float* mlp_W0 = (const float*)d_in[10];
    const float* mlp_b0 = (const float*)d_in[11];
    const float* mlp_W1 = (const float*)d_in[12];
    const float* mlp_b1 = (const float*)d_in[13];
    const float* mlp_W2 = (const float*)d_in[14];
    const float* mlp_b2 = (const float*)d_in[15];
    const float* mlp_W3 = (const float*)d_in[16];
    const float* mlp_b3 = (const float*)d_in[17];

    cudaFuncSetAttribute(mma_gemm, cudaFuncAttributeMaxDynamicSharedMemorySize, MMA_SMEM_BYTES);

    Ctx c;
    GETSYM(c.Xn, g_Xn);       GETSYM(c.sq, g_sq);      GETSYM(c.sim, g_sim);
    GETSYM(c.Ap, g_Ap);       GETSYM(c.Bp, g_Bp);      GETSYM(c.Wp, g_Wp);
    GETSYM(c.bits, g_bits);   GETSYM(c.nbr, g_nbr);    GETSYM(c.cnt, g_cnt);
    GETSYM(c.Wh, g_Wh);       GETSYM(c.s1, g_s1);      GETSYM(c.s2, g_s2);
    GETSYM(c.hidden, g_hidden); GETSYM(c.WhO, g_WhO);
    GETSYM(c.sO1, g_sO1);     GETSYM(c.sO2, g_sO2);    GETSYM(c.pair, g_pair);
    GETSYM(c.m1, g_m1);       GETSYM(c.m2, g_m2);      GETSYM(c.m3, g_m3);

    run_gat(c, user_nodes, 0, user_W_h, user_a_h, user_W_o, user_a_o, 0);
    run_gat(c, food_nodes, 1, food_W_h, food_a_h, food_W_o, food_a_o, HIDD);

    // MLP: 512 -> 512 -> 256 -> 128 -> 1  (first three layers via mma)
    pack3_kernel<<<(NNODES * 512 + 255) / 256, 256>>>(c.pair, c.Ap, 512, NNODES * 512, 0);
    packWgen3_kernel<<<(512 * 512 + 255) / 256, 256>>>(mlp_W0, c.Wp, 512, 512);
    launch_mma(c.Ap, c.Wp, c.m1, NNODES, 512, 3 * 512, mlp_b0, 1);

    pack3_kernel<<<(NNODES * 512 + 255) / 256, 256>>>(c.m1, c.Ap, 512, NNODES * 512, 0);
    packWgen3_kernel<<<(512 * 256 + 255) / 256, 256>>>(mlp_W1, c.Wp, 512, 256);
    launch_mma(c.Ap, c.Wp, c.m2, NNODES, 256, 3 * 512, mlp_b1, 1);

    pack3_kernel<<<(NNODES * 256 + 255) / 256, 256>>>(c.m2, c.Ap, 256, NNODES * 256, 0);
    packWgen3_kernel<<<(256 * 128 + 255) / 256, 256>>>(mlp_W2, c.Wp, 256, 128);
    launch_mma(c.Ap, c.Wp, c.m3, NNODES, 128, 3 * 256, mlp_b2, 1);

    mlp3_kernel<<<NNODES / 4, 128>>>(c.m3, mlp_W3, mlp_b3, (float*)d_out);

    (void)in_sizes; (void)n_in; (void)out_size;
}

// round 9
// speedup vs baseline: 2.0842x; 1.2666x over previous
#include <cuda_runtime.h>
#include <cuda_bf16.h>
#include <float.h>
#include <math.h>
#include <cstdint>

#define NNODES 2048
#define DIM    512
#define HIDD   256
#define NHEAD  4
#define TOPK   6
#define MAXD   256

// ================= scratch (device globals; per-branch where concurrent) =================
__device__ __align__(16) float g_Xn[NNODES * DIM];
__device__ __align__(16) float g_sq[2][NNODES];
__device__ __align__(16) float g_sim[2][NNODES * NNODES];
__device__ __align__(16) __nv_bfloat16 g_Ap[2][NNODES * 3 * 1024];
__device__ __align__(16) __nv_bfloat16 g_Bp[2][NNODES * 3 * DIM];
__device__ __align__(16) __nv_bfloat16 g_Wp[2][1024 * 3 * 1024];
__device__ unsigned g_bits[2][NNODES * 64];
__device__ int   g_nbr[2][NNODES * MAXD];
__device__ int   g_cnt[2][NNODES];
__device__ __align__(16) float g_Wh[2][NNODES * NHEAD * HIDD];
__device__ __align__(16) float g_s1[2][NHEAD * NNODES];
__device__ __align__(16) float g_s2[2][NHEAD * NNODES];
__device__ __align__(16) float g_hidden[2][NNODES * NHEAD * HIDD];
__device__ __align__(16) float g_WhO[2][NNODES * HIDD];
__device__ __align__(16) float g_sO1[2][NNODES];
__device__ __align__(16) float g_sO2[2][NNODES];
__device__ __align__(16) float g_pair[NNODES * 2 * HIDD];
__device__ __align__(16) float g_m1[NNODES * 512];
__device__ __align__(16) float g_m2[NNODES * 256];
__device__ __align__(16) float g_m3[NNODES * 128];

// ================= small PTX helpers =================
__device__ __forceinline__ uint32_t smem_to_u32(const void* p) {
    uint32_t a;
    asm("{ .reg .u64 t; cvta.to.shared.u64 t, %1; cvt.u32.u64 %0, t; }" : "=r"(a) : "l"(p));
    return a;
}
__device__ __forceinline__ void cp_async16(uint32_t saddr, const void* gaddr) {
    asm volatile("cp.async.cg.shared.global [%0], [%1], 16;" :: "r"(saddr), "l"(gaddr));
}
__device__ __forceinline__ void cp_commit() { asm volatile("cp.async.commit_group;"); }
template <int N>
__device__ __forceinline__ void cp_wait() { asm volatile("cp.async.wait_group %0;" :: "n"(N)); }

__device__ __forceinline__ void ldmatrix_x4(uint32_t* r, uint32_t addr) {
    asm volatile("ldmatrix.sync.aligned.m8n8.x4.shared.b16 {%0,%1,%2,%3}, [%4];"
                 : "=r"(r[0]), "=r"(r[1]), "=r"(r[2]), "=r"(r[3]) : "r"(addr));
}
__device__ __forceinline__ void ldmatrix_x2(uint32_t* r, uint32_t addr) {
    asm volatile("ldmatrix.sync.aligned.m8n8.x2.shared.b16 {%0,%1}, [%2];"
                 : "=r"(r[0]), "=r"(r[1]) : "r"(addr));
}
__device__ __forceinline__ void mma16816(float* c, const uint32_t* a, const uint32_t* b) {
    asm volatile(
        "mma.sync.aligned.m16n8k16.row.col.f32.bf16.bf16.f32 "
        "{%0,%1,%2,%3}, {%4,%5,%6,%7}, {%8,%9}, {%0,%1,%2,%3};"
        : "+f"(c[0]), "+f"(c[1]), "+f"(c[2]), "+f"(c[3])
        : "r"(a[0]), "r"(a[1]), "r"(a[2]), "r"(a[3]), "r"(b[0]), "r"(b[1]));
}

// ================= row norms =================
__global__ void rowstat_kernel(const float* __restrict__ X, float* __restrict__ Xn,
                               float* __restrict__ sq) {
    int i = blockIdx.x;
    int t = threadIdx.x;  // 256
    float s = 0.f;
    for (int d = t; d < DIM; d += 256) { float v = X[(size_t)i * DIM + d]; s += v * v; }
    __shared__ float sh[256];
    sh[t] = s; __syncthreads();
    for (int k = 128; k; k >>= 1) { if (t < k) sh[t] += sh[t + k]; __syncthreads(); }
    float tot = sh[0];
    if (t == 0) sq[i] = tot;
    if (Xn) {
        float inv = 1.0f / sqrtf(tot);
        for (int d = t; d < DIM; d += 256) Xn[(size_t)i * DIM + d] = X[(size_t)i * DIM + d] * inv;
    }
}

// ================= packing =================
// A pattern: [hi | hi | lo] ; B pattern: [hi | lo | hi]
__global__ void pack3_kernel(const float* __restrict__ src, __nv_bfloat16* __restrict__ dst,
                             int K, int total, int pat) {
    int idx = blockIdx.x * blockDim.x + threadIdx.x;
    if (idx >= total) return;
    int row = idx / K, col = idx % K;
    float x = src[idx];
    __nv_bfloat16 hi = __float2bfloat16(x);
    __nv_bfloat16 lo = __float2bfloat16(x - __bfloat162float(hi));
    size_t base = (size_t)row * 3 * K + col;
    dst[base] = hi;
    dst[base + K] = pat ? lo : hi;
    dst[base + 2 * K] = pat ? hi : lo;
}

// fused: one read, both patterns (for sim where A and B come from same matrix)
__global__ void pack3AB_kernel(const float* __restrict__ src, __nv_bfloat16* __restrict__ dA,
                               __nv_bfloat16* __restrict__ dB, int K, int total) {
    int idx = blockIdx.x * blockDim.x + threadIdx.x;
    if (idx >= total) return;
    int row = idx / K, col = idx % K;
    float x = src[idx];
    __nv_bfloat16 hi = __float2bfloat16(x);
    __nv_bfloat16 lo = __float2bfloat16(x - __bfloat162float(hi));
    size_t base = (size_t)row * 3 * K + col;
    dA[base] = hi; dA[base + K] = hi; dA[base + 2 * K] = lo;
    dB[base] = hi; dB[base + K] = lo; dB[base + 2 * K] = hi;
}

// W_h [H, DIM, HIDD] -> [H*HIDD, 3*DIM] pat B
__global__ void packWh3_kernel(const float* __restrict__ W, __nv_bfloat16* __restrict__ dst) {
    int idx = blockIdx.x * blockDim.x + threadIdx.x;
    if (idx >= NHEAD * HIDD * DIM) return;
    int n = idx / DIM, k = idx % DIM;
    int h = n / HIDD, hid = n % HIDD;
    float w = W[(size_t)h * DIM * HIDD + (size_t)k * HIDD + hid];
    __nv_bfloat16 hi = __float2bfloat16(w);
    __nv_bfloat16 lo = __float2bfloat16(w - __bfloat162float(hi));
    size_t base = (size_t)n * 3 * DIM + k;
    dst[base] = hi; dst[base + DIM] = lo; dst[base + 2 * DIM] = hi;
}

// generic weight W [K, N] -> [N, 3K] pat B
__global__ void packWgen3_kernel(const float* __restrict__ W, __nv_bfloat16* __restrict__ dst,
                                 int K, int N) {
    int idx = blockIdx.x * blockDim.x + threadIdx.x;
    if (idx >= N * K) return;
    int n = idx / K, k = idx % K;
    float w = W[(size_t)k * N + n];
    __nv_bfloat16 hi = __float2bfloat16(w);
    __nv_bfloat16 lo = __float2bfloat16(w - __bfloat162float(hi));
    size_t base = (size_t)n * 3 * K + k;
    dst[base] = hi; dst[base + K] = lo; dst[base + 2 * K] = hi;
}

// ================= mma.sync bf16 GEMM, 3-stage cp.async pipeline =================
// C[M,Nc] = A[M,K] @ B[Nc,K]^T ; 128x128 tile, BK=64, SW128 swizzle, 8 warps (2x4).
#define MMA_STAGES 3
#define MMA_SMEM_BYTES (MMA_STAGES * 32768)

__global__ void __launch_bounds__(256, 2)
mma_gemm(const __nv_bfloat16* __restrict__ A, const __nv_bfloat16* __restrict__ B,
         float* __restrict__ C, int Nc, int K, const float* __restrict__ bias, int relu) {
    extern __shared__ char sm[];
    const int tid = threadIdx.x;
    const int lane = tid & 31;
    const int warp = tid >> 5;
    const int wm = warp >> 2;   // 0..1
    const int wn = warp & 3;    // 0..3
    const int row0 = blockIdx.y * 128;
    const int col0 = blockIdx.x * 128;
    const uint32_t sbase = smem_to_u32(sm);

    const __nv_bfloat16* Aptr = A + (size_t)row0 * K;
    const __nv_bfloat16* Bptr = B + (size_t)col0 * K;

    float acc[4][4][4];
#pragma unroll
    for (int mt = 0; mt < 4; mt++)
#pragma unroll
        for (int nt = 0; nt < 4; nt++)
#pragma unroll
            for (int q = 0; q < 4; q++) acc[mt][nt][q] = 0.f;

    const int nch = K / 64;
    auto issue = [&](int c) {
        uint32_t base = sbase + (c % MMA_STAGES) * 32768;
        int koff = c * 64;
#pragma unroll
        for (int l = 0; l < 4; l++) {
            int idx = tid + l * 256;
            int r = idx >> 3;
            int jb = (idx & 7) * 16;
            unsigned off = r * 128 + jb;
            unsigned sw = off ^ ((off >> 3) & 0x70);
            cp_async16(base + sw, (const char*)(Aptr + (size_t)r * K + koff) + jb);
            cp_async16(base + 16384 + sw, (const char*)(Bptr + (size_t)r * K + koff) + jb);
        }
        cp_commit();
    };

    issue(0);
    issue(1);
    for (int c = 0; c < nch; c++) {
        cp_wait<1>();
        __syncthreads();
        if (c + 2 < nch) issue(c + 2); else cp_commit();
        uint32_t aBase = sbase + (c % MMA_STAGES) * 32768;
        uint32_t bBase = aBase + 16384;
#pragma unroll
        for (int ks = 0; ks < 4; ks++) {
            uint32_t af[4][4], bf[4][2];
#pragma unroll
            for (int mt = 0; mt < 4; mt++) {
                int r = wm * 64 + mt * 16 + (lane & 15);
                unsigned off = r * 128 + ks * 32 + (lane >> 4) * 16;
                unsigned sw = off ^ ((off >> 3) & 0x70);
                ldmatrix_x4(af[mt], aBase + sw);
            }
#pragma unroll
            for (int nt = 0; nt < 4; nt++) {
                int r = wn * 32 + nt * 8 + (lane & 7);
                unsigned off = r * 128 + ks * 32 + ((lane >> 3) & 1) * 16;
                unsigned sw = off ^ ((off >> 3) & 0x70);
                ldmatrix_x2(bf[nt], bBase + sw);
            }
#pragma unroll
            for (int mt = 0; mt < 4; mt++)
#pragma unroll
                for (int nt = 0; nt < 4; nt++)
                    mma16816(acc[mt][nt], af[mt], bf[nt]);
        }
        __syncthreads();
    }

#pragma unroll
    for (int mt = 0; mt < 4; mt++) {
        int r0 = row0 + wm * 64 + mt * 16 + (lane >> 2);
#pragma unroll
        for (int nt = 0; nt < 4; nt++) {
            int cc = col0 + wn * 32 + nt * 8 + (lane & 3) * 2;
            float b0 = 0.f, b1 = 0.f;
            if (bias) { b0 = bias[cc]; b1 = bias[cc + 1]; }
            float v0 = acc[mt][nt][0] + b0, v1 = acc[mt][nt][1] + b1;
            float v2 = acc[mt][nt][2] + b0, v3 = acc[mt][nt][3] + b1;
            if (relu) {
                v0 = fmaxf(v0, 0.f); v1 = fmaxf(v1, 0.f);
                v2 = fmaxf(v2, 0.f); v3 = fmaxf(v3, 0.f);
            }
            *(float2*)(C + (size_t)r0 * Nc + cc) = make_float2(v0, v1);
            *(float2*)(C + (size_t)(r0 + 8) * Nc + cc) = make_float2(v2, v3);
        }
    }
}

// ================= top-6 + edges into bitmask =================
__device__ __forceinline__ bool tk_better(float v1, int i1, float v2, int i2) {
    return (v1 > v2) || (v1 == v2 && i1 < i2);
}
__global__ void topk_kernel2(const float* __restrict__ sim, const float* __restrict__ sq,
                             unsigned* __restrict__ bits, int mode) {
    const int i = blockIdx.x;
    const int t = threadIdx.x;  // 128
    const int w = t >> 5, lane = t & 31;
    float bv[TOPK]; int bi[TOPK];
#pragma unroll
    for (int k = 0; k < TOPK; k++) { bv[k] = -FLT_MAX; bi[k] = 0x7fffffff; }
    const float4* row = (const float4*)(sim + (size_t)i * NNODES);
#pragma unroll
    for (int it = 0; it < 4; it++) {
        int c4 = w * 128 + it * 32 + lane;
        float4 v = row[c4];
        float e[4] = {v.x, v.y, v.z, v.w};
#pragma unroll
        for (int j = 0; j < 4; j++) {
            int c = c4 * 4 + j;
            float key = (mode == 0) ? (2.f * e[j] - sq[c]) : e[j];
            if (tk_better(key, c, bv[TOPK - 1], bi[TOPK - 1])) {
                bv[TOPK - 1] = key; bi[TOPK - 1] = c;
#pragma unroll
                for (int k = TOPK - 1; k > 0; k--) {
                    if (tk_better(bv[k], bi[k], bv[k - 1], bi[k - 1])) {
                        float tv = bv[k]; bv[k] = bv[k - 1]; bv[k - 1] = tv;
                        int ti = bi[k]; bi[k] = bi[k - 1]; bi[k - 1] = ti;
                    } else break;
                }
            }
        }
    }
    __shared__ float sv[4 * TOPK];
    __shared__ int si[4 * TOPK];
    {
        int p = 0;
#pragma unroll
        for (int r = 0; r < TOPK; r++) {
            float v = (p < TOPK) ? bv[p] : -FLT_MAX;
            int id = (p < TOPK) ? bi[p] : 0x7fffffff;
#pragma unroll
            for (int s = 16; s; s >>= 1) {
                float ov = __shfl_xor_sync(0xffffffffu, v, s);
                int oi = __shfl_xor_sync(0xffffffffu, id, s);
                if (tk_better(ov, oi, v, id)) { v = ov; id = oi; }
            }
            if (p < TOPK && bi[p] == id) p++;
            if (lane == 0) { sv[w * TOPK + r] = v; si[w * TOPK + r] = id; }
        }
    }
    __syncthreads();
    if (w == 0) {
        float v = (lane < 4 * TOPK) ? sv[lane] : -FLT_MAX;
        int id = (lane < 4 * TOPK) ? si[lane] : 0x7fffffff;
#pragma unroll
        for (int r = 0; r < TOPK; r++) {
            float mv = v; int mi = id;
#pragma unroll
            for (int s = 16; s; s >>= 1) {
                float ov = __shfl_xor_sync(0xffffffffu, mv, s);
                int oi = __shfl_xor_sync(0xffffffffu, mi, s);
                if (tk_better(ov, oi, mv, mi)) { mv = ov; mi = oi; }
            }
            if (id == mi) { v = -FLT_MAX; id = 0x7fffffff; }
            if (lane == 0 && mi < NNODES) {
                int j = mi;
                bool ok = (j != i) && (mode == 0 || mv > 0.f);
                if (ok) {
                    atomicOr(&bits[(size_t)i * 64 + (j >> 5)], 1u << (j & 31));
                    atomicOr(&bits[(size_t)j * 64 + (i >> 5)], 1u << (i & 31));
                }
            }
        }
    }
}

// ================= neighbor lists from bitmask =================
__global__ void build_nbr_bits(const unsigned* __restrict__ bits, int* __restrict__ nbr,
                               int* __restrict__ cnt) {
    int warp = (blockIdx.x * blockDim.x + threadIdx.x) >> 5;
    int lane = threadIdx.x & 31;
    if (warp >= NNODES) return;
    const int i = warp;
    unsigned w0 = bits[(size_t)i * 64 + 2 * lane];
    unsigned w1 = bits[(size_t)i * 64 + 2 * lane + 1];
    int c = __popc(w0) + __popc(w1);
    int off = c;
#pragma unroll
    for (int s = 1; s < 32; s <<= 1) {
        int v = __shfl_up_sync(0xffffffffu, off, s);
        if (lane >= s) off += v;
    }
    int total = __shfl_sync(0xffffffffu, off, 31);
    off -= c;
    if (lane == 0) cnt[i] = total > MAXD ? MAXD : total;
    int base = lane * 64;
    int pos = off;
    while (w0) {
        int b = __ffs(w0) - 1; w0 &= w0 - 1;
        if (pos < MAXD) nbr[(size_t)i * MAXD + pos] = base + b;
        pos++;
    }
    base += 32;
    while (w1) {
        int b = __ffs(w1) - 1; w1 &= w1 - 1;
        if (pos < MAXD) nbr[(size_t)i * MAXD + pos] = base + b;
        pos++;
    }
}

// ================= attention scalars =================
__global__ void s12_kernel(const float* __restrict__ Wh, const float* __restrict__ a,
                           float* __restrict__ s1, float* __restrict__ s2, int Hn) {
    int warp = (blockIdx.x * blockDim.x + threadIdx.x) >> 5;
    int lane = threadIdx.x & 31;
    if (warp >= NNODES * Hn) return;
    int i = warp / Hn, h = warp % Hn;
    const float* w = Wh + (size_t)i * Hn * HIDD + (size_t)h * HIDD;
    const float* av = a + (size_t)h * 2 * HIDD;
    float a1 = 0.f, a2 = 0.f;
    for (int d = lane; d < HIDD; d += 32) {
        float x = w[d];
        a1 += x * av[d];
        a2 += x * av[HIDD + d];
    }
    for (int s = 16; s; s >>= 1) {
        a1 += __shfl_down_sync(0xffffffffu, a1, s);
        a2 += __shfl_down_sync(0xffffffffu, a2, s);
    }
    if (lane == 0) { s1[h * NNODES + i] = a1; s2[h * NNODES + i] = a2; }
}

// ================= sparse softmax-aggregate + ELU =================
__global__ void aggregate_kernel(const float* __restrict__ Wh,
                                 const int* __restrict__ nbr, const int* __restrict__ cnt,
                                 const float* __restrict__ s1, const float* __restrict__ s2,
                                 float* __restrict__ out, int Hn, int outStride, int outOff) {
    int b = blockIdx.x;
    int i = b / Hn, h = b % Hn;
    int t = threadIdx.x;  // 256 == HIDD
    __shared__ float w[MAXD];
    __shared__ float s_sum;
    int c = cnt[i];
    const int* nb = nbr + (size_t)i * MAXD;
    if (t < 32) {
        float m = -FLT_MAX;
        float base = s1[h * NNODES + i];
        for (int j = t; j < c; j += 32) {
            float e = base + s2[h * NNODES + nb[j]];
            e = e > 0.f ? e : 0.2f * e;  // leaky relu
            w[j] = e;
            m = fmaxf(m, e);
        }
        for (int s = 16; s; s >>= 1) m = fmaxf(m, __shfl_xor_sync(0xffffffffu, m, s));
        float sum = 0.f;
        for (int j = t; j < c; j += 32) {
            float ex = expf(w[j] - m);
            w[j] = ex;
            sum += ex;
        }
        for (int s = 16; s; s >>= 1) sum += __shfl_xor_sync(0xffffffffu, sum, s);
        if (t == 0) s_sum = sum;
    }
    __syncthreads();
    float acc = 0.f;
    for (int j = 0; j < c; j++)
        acc += w[j] * Wh[(size_t)nb[j] * (Hn * HIDD) + (size_t)h * HIDD + t];
    float v = acc / s_sum;
    v = v > 0.f ? v : expm1f(v);  // elu
    out[(size_t)i * outStride + outOff + (size_t)h * HIDD + t] = v;
}

// ================= final MLP layer (N=1) =================
__global__ void mlp3_kernel(const float* __restrict__ Xin, const float* __restrict__ W,
                            const float* __restrict__ b, float* __restrict__ out) {
    int warp = (blockIdx.x * blockDim.x + threadIdx.x) >> 5;
    int lane = threadIdx.x & 31;
    if (warp >= NNODES) return;
    float acc = 0.f;
    for (int d = lane; d < 128; d += 32) acc += Xin[(size_t)warp * 128 + d] * W[d];
    for (int s = 16; s; s >>= 1) acc += __shfl_down_sync(0xffffffffu, acc, s);
    if (lane == 0) out[warp] = acc + b[0];
}

// ================= host side =================
#define GETSYM(p, s)                               \
    do {                                           \
        void* _tmp = nullptr;                      \
        cudaGetSymbolAddress(&_tmp, s);            \
        p = (decltype(p))_tmp;                     \
    } while (0)

struct Branch {
    float *sq, *sim, *Wh, *s1, *s2, *hidden, *WhO, *sO1, *sO2;
    __nv_bfloat16 *Ap, *Bp, *Wp;
    unsigned* bits;
    int *nbr, *cnt;
};

static inline void launch_mma(cudaStream_t st, const __nv_bfloat16* A, const __nv_bfloat16* B,
                              float* C, int M, int Nc, int Kp, const float* bias, int relu) {
    mma_gemm<<<dim3(Nc / 128, M / 128), 256, MMA_SMEM_BYTES, st>>>(A, B, C, Nc, Kp, bias, relu);
}

static void run_gat(cudaStream_t st, const Branch& b, const float* X, float* Xn, int mode,
                    const float* W_h, const float* a_h, const float* W_o, const float* a_o,
                    float* pair, int pairOff) {
    rowstat_kernel<<<NNODES, 256, 0, st>>>(X, mode ? Xn : nullptr, b.sq);
    const float* Xs = mode ? Xn : X;
    // sim = Xs @ Xs^T (split bf16)
    pack3AB_kernel<<<(NNODES * DIM + 255) / 256, 256, 0, st>>>(Xs, b.Ap, b.Bp, DIM, NNODES * DIM);
    launch_mma(st, b.Ap, b.Bp, b.sim, NNODES, NNODES, 3 * DIM, nullptr, 0);
    cudaMemsetAsync(b.bits, 0, (size_t)NNODES * 64 * sizeof(unsigned), st);
    topk_kernel2<<<NNODES, 128, 0, st>>>(b.sim, b.sq, b.bits, mode);
    build_nbr_bits<<<NNODES / 8, 256, 0, st>>>(b.bits, b.nbr, b.cnt);
    // Wh = X @ W_h
    if (mode)
        pack3_kernel<<<(NNODES * DIM + 255) / 256, 256, 0, st>>>(X, b.Ap, DIM, NNODES * DIM, 0);
    packWh3_kernel<<<(NHEAD * HIDD * DIM + 255) / 256, 256, 0, st>>>(W_h, b.Wp);
    launch_mma(st, b.Ap, b.Wp, b.Wh, NNODES, NHEAD * HIDD, 3 * DIM, nullptr, 0);
    s12_kernel<<<(NNODES * NHEAD) / 4, 128, 0, st>>>(b.Wh, a_h, b.s1, b.s2, NHEAD);
    aggregate_kernel<<<NNODES * NHEAD, 256, 0, st>>>(b.Wh, b.nbr, b.cnt, b.s1, b.s2, b.hidden,
                                                     NHEAD, NHEAD * HIDD, 0);
    // WhO = hidden @ W_o
    pack3_kernel<<<(NNODES * 1024 + 255) / 256, 256, 0, st>>>(b.hidden, b.Ap, 1024,
                                                              NNODES * 1024, 0);
    packWgen3_kernel<<<(1024 * HIDD + 255) / 256, 256, 0, st>>>(W_o, b.Wp, 1024, HIDD);
    launch_mma(st, b.Ap, b.Wp, b.WhO, NNODES, HIDD, 3 * 1024, nullptr, 0);
    s12_kernel<<<NNODES / 4, 128, 0, st>>>(b.WhO, a_o, b.sO1, b.sO2, 1);
    aggregate_kernel<<<NNODES, 256, 0, st>>>(b.WhO, b.nbr, b.cnt, b.sO1, b.sO2, pair, 1, 2 * HIDD,
                                             pairOff);
}

extern "C" void kernel_launch(void* const* d_in, const int* in_sizes, int n_in,
                              void* d_out, int out_size) {
    const float* user_nodes = (const float*)d_in[0];
    const float* food_nodes = (const float*)d_in[1];
    const float* user_W_h = (const float*)d_in[2];
    const float* user_a_h = (const float*)d_in[3];
    const float* user_W_o = (const float*)d_in[4];
    const float* user_a_o = (const float*)d_in[5];
    const float* food_W_h = (const float*)d_in[6];
    const float* food_a_h = (const float*)d_in[7];
    const float* food_W_o = (const float*)d_in[8];
    const float* food_a_o = (const float*)d_in[9];
    const float* mlp_W0 = (const float*)d_in[10];
    const float* mlp_b0 = (const float*)d_in[11];
    const float* mlp_W1 = (const float*)d_in[12];
    const float* mlp_b1 = (const float*)d_in[13];
    const float* mlp_W2 = (const float*)d_in[14];
    const float* mlp_b2 = (const float*)d_in[15];
    const float* mlp_W3 = (const float*)d_in[16];
    const float* mlp_b3 = (const float*)d_in[17];

    static cudaStream_t s_food = nullptr;
    static cudaEvent_t ev_fork = nullptr, ev_join = nullptr;
    if (!s_food) {
        cudaStreamCreateWithFlags(&s_food, cudaStreamNonBlocking);
        cudaEventCreateWithFlags(&ev_fork, cudaEventDisableTiming);
        cudaEventCreateWithFlags(&ev_join, cudaEventDisableTiming);
        cudaFuncSetAttribute(mma_gemm, cudaFuncAttributeMaxDynamicSharedMemorySize,
                             MMA_SMEM_BYTES);
    }

    float* Xn;  GETSYM(Xn, g_Xn);
    float* pair; GETSYM(pair, g_pair);
    float *m1, *m2, *m3;
    GETSYM(m1, g_m1); GETSYM(m2, g_m2); GETSYM(m3, g_m3);

    Branch br[2];
    for (int b = 0; b < 2; b++) {
        void* t;
        cudaGetSymbolAddress(&t, g_sq);     br[b].sq  = (float*)t + (size_t)b * NNODES;
        cudaGetSymbolAddress(&t, g_sim);    br[b].sim = (float*)t + (size_t)b * NNODES * NNODES;
        cudaGetSymbolAddress(&t, g_Ap);     br[b].Ap  = (__nv_bfloat16*)t + (size_t)b * NNODES * 3 * 1024;
        cudaGetSymbolAddress(&t, g_Bp);     br[b].Bp  = (__nv_bfloat16*)t + (size_t)b * NNODES * 3 * DIM;
        cudaGetSymbolAddress(&t, g_Wp);     br[b].Wp  = (__nv_bfloat16*)t + (size_t)b * 1024 * 3 * 1024;
        cudaGetSymbolAddress(&t, g_bits);   br[b].bits = (unsigned*)t + (size_t)b * NNODES * 64;
        cudaGetSymbolAddress(&t, g_nbr);    br[b].nbr = (int*)t + (size_t)b * NNODES * MAXD;
        cudaGetSymbolAddress(&t, g_cnt);    br[b].cnt = (int*)t + (size_t)b * NNODES;
        cudaGetSymbolAddress(&t, g_Wh);     br[b].Wh  = (float*)t + (size_t)b * NNODES * NHEAD * HIDD;
        cudaGetSymbolAddress(&t, g_s1);     br[b].s1  = (float*)t + (size_t)b * NHEAD * NNODES;
        cudaGetSymbolAddress(&t, g_s2);     br[b].s2  = (float*)t + (size_t)b * NHEAD * NNODES;
        cudaGetSymbolAddress(&t, g_hidden); br[b].hidden = (float*)t + (size_t)b * NNODES * NHEAD * HIDD;
        cudaGetSymbolAddress(&t, g_WhO);    br[b].WhO = (float*)t + (size_t)b * NNODES * HIDD;
        cudaGetSymbolAddress(&t, g_sO1);    br[b].sO1 = (float*)t + (size_t)b * NNODES;
        cudaGetSymbolAddress(&t, g_sO2);    br[b].sO2 = (float*)t + (size_t)b * NNODES;
    }

    // fork: food branch runs on s_food concurrently with user branch on stream 0
    cudaEventRecord(ev_fork, 0);
    cudaStreamWaitEvent(s_food, ev_fork, 0);

    run_gat(0, br[0], user_nodes, nullptr, 0, user_W_h, user_a_h, user_W_o, user_a_o, pair, 0);
    run_gat(s_food, br[1], food_nodes, Xn, 1, food_W_h, food_a_h, food_W_o, food_a_o, pair, HIDD);

    // join
    cudaEventRecord(ev_join, s_food);
    cudaStreamWaitEvent(0, ev_join, 0);

    // MLP: 512 -> 512 -> 256 -> 128 -> 1
    pack3_kernel<<<(NNODES * 512 + 255) / 256, 256>>>(pair, br[0].Ap, 512, NNODES * 512, 0);
    packWgen3_kernel<<<(512 * 512 + 255) / 256, 256>>>(mlp_W0, br[0].Wp, 512, 512);
    launch_mma(0, br[0].Ap, br[0].Wp, m1, NNODES, 512, 3 * 512, mlp_b0, 1);

    pack3_kernel<<<(NNODES * 512 + 255) / 256, 256>>>(m1, br[0].Ap, 512, NNODES * 512, 0);
    packWgen3_kernel<<<(512 * 256 + 255) / 256, 256>>>(mlp_W1, br[0].Wp, 512, 256);
    launch_mma(0, br[0].Ap, br[0].Wp, m2, NNODES, 256, 3 * 512, mlp_b1, 1);

    pack3_kernel<<<(NNODES * 256 + 255) / 256, 256>>>(m2, br[0].Ap, 256, NNODES * 256, 0);
    packWgen3_kernel<<<(256 * 128 + 255) / 256, 256>>>(mlp_W2, br[0].Wp, 256, 128);
    launch_mma(0, br[0].Ap, br[0].Wp, m3, NNODES, 128, 3 * 256, mlp_b2, 1);

    mlp3_kernel<<<NNODES / 4, 128>>>(m3, mlp_W3, mlp_b3, (float*)d_out);

    (void)in_sizes; (void)n_in; (void)out_size;
}